// round 9
// baseline (speedup 1.0000x reference)
#include <cuda_runtime.h>
#include <cuda_bf16.h>
#include <cstdint>

// Problem constants
#define SEQ    4096     // H*W
#define DMODEL 512
#define NHEADS 8
#define DHEAD  64
#define CAN    64       // canvas H = W
#define BATCH  2

typedef unsigned int u32;
typedef unsigned long long u64;
typedef unsigned short u16;

// Scratch (device globals: allocation-free rule)
__device__ float g_qkv[BATCH * SEQ * 3 * DMODEL];            // fp32 [b,s,1536]
__device__ __nv_bfloat16 g_xh[BATCH * SEQ * DMODEL];
__device__ __nv_bfloat16 g_xl[BATCH * SEQ * DMODEL];
__device__ __nv_bfloat16 g_wqh[3 * DMODEL * DMODEL];
__device__ __nv_bfloat16 g_wql[3 * DMODEL * DMODEL];
__device__ __nv_bfloat16 g_woh[DMODEL * DMODEL];
__device__ __nv_bfloat16 g_wol[DMODEL * DMODEL];
__device__ __nv_bfloat16 g_ath[BATCH * SEQ * DMODEL];
__device__ __nv_bfloat16 g_atl[BATCH * SEQ * DMODEL];
// per-head split Q/K/V: [b, nh, s, 64]
#define HEADELEMS (BATCH * NHEADS * SEQ * DHEAD)
__device__ __nv_bfloat16 g_Qh[HEADELEMS];
__device__ __nv_bfloat16 g_Ql[HEADELEMS];
__device__ __nv_bfloat16 g_Kh[HEADELEMS];
__device__ __nv_bfloat16 g_Kl[HEADELEMS];
__device__ __nv_bfloat16 g_Vh[HEADELEMS];
__device__ __nv_bfloat16 g_Vl[HEADELEMS];
__device__ __nv_bfloat16 g_zero[8];              // zero-initialized, cp.async pad src

__device__ __forceinline__ u32 smem_u32(const void* p) {
    u32 a;
    asm("{ .reg .u64 t; cvta.to.shared.u64 t, %1; cvt.u32.u64 %0, t; }" : "=r"(a) : "l"(p));
    return a;
}
__device__ __forceinline__ u16 bfbits(__nv_bfloat16 h) { return *(u16*)&h; }
__device__ __forceinline__ u32 cvt_bf16x2(float hi, float lo) {
    u32 r; asm("cvt.rn.bf16x2.f32 %0, %1, %2;" : "=r"(r) : "f"(hi), "f"(lo)); return r;
}
__device__ __forceinline__ float bf_lo(u32 v) {
    __nv_bfloat16 h = *(__nv_bfloat16*)&v; return __bfloat162float(h);
}
__device__ __forceinline__ float bf_hi(u32 v) {
    u16 b = (u16)(v >> 16); __nv_bfloat16 h = *(__nv_bfloat16*)&b; return __bfloat162float(h);
}

// ---------------------------------------------------------------------------
// fp32 -> bf16 hi/lo split (elementwise)
// ---------------------------------------------------------------------------
__global__ __launch_bounds__(256) void split_kernel(const float* __restrict__ in,
                                                    __nv_bfloat16* __restrict__ hi,
                                                    __nv_bfloat16* __restrict__ lo,
                                                    int n4)
{
    const int i = blockIdx.x * 256 + threadIdx.x;
    if (i >= n4) return;
    float4 f = ((const float4*)in)[i];
    float v[4] = {f.x, f.y, f.z, f.w};
    ushort4 hv, lv;
    u16* hp = &hv.x; u16* lp = &lv.x;
#pragma unroll
    for (int j = 0; j < 4; j++) {
        __nv_bfloat16 h = __float2bfloat16_rn(v[j]);
        __nv_bfloat16 l = __float2bfloat16_rn(v[j] - __bfloat162float(h));
        hp[j] = bfbits(h); lp[j] = bfbits(l);
    }
    ((ushort4*)hi)[i] = hv;
    ((ushort4*)lo)[i] = lv;
}

// ---------------------------------------------------------------------------
// qkv fp32 [b,s,1536] -> per-head bf16 hi/lo [b,nh,s,64] for Q,K,V
// ---------------------------------------------------------------------------
__global__ __launch_bounds__(256) void qkv_split_kernel(const float* __restrict__ qkv)
{
    const int i4 = blockIdx.x * 256 + threadIdx.x;           // float4 index
    const int N4 = BATCH * SEQ * 384;                        // 1536/4 per row
    if (i4 >= N4) return;
    const int row = i4 / 384;
    const int col = (i4 - row * 384) * 4;
    const int t   = col >> 9;                                // 0=q 1=k 2=v
    const int nh  = (col >> 6) & 7;
    const int d   = col & 63;
    const int b   = row >> 12;
    const int s   = row & 4095;

    float4 f = ((const float4*)qkv)[i4];
    float v[4] = {f.x, f.y, f.z, f.w};
    ushort4 hv, lv;
    u16* hp = &hv.x; u16* lp = &lv.x;
#pragma unroll
    for (int j = 0; j < 4; j++) {
        __nv_bfloat16 h = __float2bfloat16_rn(v[j]);
        __nv_bfloat16 l = __float2bfloat16_rn(v[j] - __bfloat162float(h));
        hp[j] = bfbits(h); lp[j] = bfbits(l);
    }
    __nv_bfloat16* dh = (t == 0) ? g_Qh : (t == 1) ? g_Kh : g_Vh;
    __nv_bfloat16* dl = (t == 0) ? g_Ql : (t == 1) ? g_Kl : g_Vl;
    const size_t o = ((size_t)(b * NHEADS + nh) * SEQ + s) * DHEAD + d;
    *(ushort4*)(dh + o) = hv;
    *(ushort4*)(dl + o) = lv;
}

// ---------------------------------------------------------------------------
// bf16x3-split GEMM, cp.async 3-stage pipeline, 256 threads, 2 CTAs/SM.
// (round-7/8 winner, unchanged)
// ---------------------------------------------------------------------------
#define TILEB   8192
#define STAGEB  (4 * TILEB)
#define STAGES  3
#define GEMM_SMEM (STAGES * STAGEB)

__device__ __forceinline__ void ldsm_x4(u32& r0, u32& r1, u32& r2, u32& r3, u32 addr) {
    asm volatile("ldmatrix.sync.aligned.m8n8.x4.shared.b16 {%0,%1,%2,%3}, [%4];"
                 : "=r"(r0), "=r"(r1), "=r"(r2), "=r"(r3) : "r"(addr));
}
__device__ __forceinline__ void ldsm_x4_t(u32& r0, u32& r1, u32& r2, u32& r3, u32 addr) {
    asm volatile("ldmatrix.sync.aligned.m8n8.x4.trans.shared.b16 {%0,%1,%2,%3}, [%4];"
                 : "=r"(r0), "=r"(r1), "=r"(r2), "=r"(r3) : "r"(addr));
}
__device__ __forceinline__ void mma_bf16(float* c, const u32* a, u32 b0, u32 b1) {
    asm volatile("mma.sync.aligned.m16n8k16.row.col.f32.bf16.bf16.f32 "
                 "{%0,%1,%2,%3}, {%4,%5,%6,%7}, {%8,%9}, {%0,%1,%2,%3};"
                 : "+f"(c[0]), "+f"(c[1]), "+f"(c[2]), "+f"(c[3])
                 : "r"(a[0]), "r"(a[1]), "r"(a[2]), "r"(a[3]), "r"(b0), "r"(b1));
}
__device__ __forceinline__ void cp16(u32 daddr, const void* src) {
    asm volatile("cp.async.cg.shared.global [%0], [%1], 16;" :: "r"(daddr), "l"(src));
}

__global__ __launch_bounds__(256, 2)
void gemm_mma(const __nv_bfloat16* __restrict__ Ah, const __nv_bfloat16* __restrict__ Al,
              const __nv_bfloat16* __restrict__ Bh, const __nv_bfloat16* __restrict__ Bl,
              float* __restrict__ C, int M, int N, int K)
{
    extern __shared__ char smc[];
    const u32 sb = smem_u32(smc);

    const int tid  = threadIdx.x;
    const int wid  = tid >> 5, lane = tid & 31;
    const int wm   = wid & 1;
    const int wn   = wid >> 1;
    const int bm   = blockIdx.y * 128;
    const int bn   = blockIdx.x * 128;

    const int ra  = lane & 15;
    const int ca  = lane >> 4;
    const int swa = (ra >> 1) & 3;
    const int rb  = (lane & 7) + ((lane >> 4) & 1) * 8;
    const int cbv = (lane >> 3) & 1;
    const int swb = (rb >> 1) & 3;

    float acc[4][4][4];
#pragma unroll
    for (int i = 0; i < 4; i++)
#pragma unroll
        for (int j = 0; j < 4; j++)
#pragma unroll
            for (int r = 0; r < 4; r++) acc[i][j][r] = 0.f;

    const int NC = K / 32;

#define LOAD_CHUNK(kc, stg)                                                        \
    {                                                                              \
        const u32 stbase = sb + (u32)(stg) * STAGEB;                               \
        _Pragma("unroll")                                                          \
        for (int i = 0; i < 8; i++) {                                              \
            const int idx = tid + i * 256;                                         \
            const int mat = idx >> 9;                                              \
            const int rem = idx & 511;                                             \
            const int row = rem >> 2;                                              \
            const int c   = rem & 3;                                               \
            const u32 daddr = stbase + (u32)mat * TILEB + (u32)row * 64u           \
                              + (u32)((c ^ ((row >> 1) & 3)) * 16);                \
            const __nv_bfloat16* g = (mat == 0) ? Ah : (mat == 1) ? Al             \
                                     : (mat == 2) ? Bh : Bl;                       \
            const int grow = ((mat < 2) ? bm : bn) + row;                          \
            cp16(daddr, g + (size_t)grow * K + (kc) + c * 8);                      \
        }                                                                          \
    }

    LOAD_CHUNK(0, 0);
    asm volatile("cp.async.commit_group;" ::: "memory");
    LOAD_CHUNK(32, 1);
    asm volatile("cp.async.commit_group;" ::: "memory");

    int st = 0, ldst = 2;
    for (int ch = 0; ch < NC; ch++) {
        asm volatile("cp.async.wait_group %0;" :: "n"(1) : "memory");
        __syncthreads();

        if (ch + 2 < NC) {
            LOAD_CHUNK((ch + 2) * 32, ldst);
            if (++ldst == STAGES) ldst = 0;
        }
        asm volatile("cp.async.commit_group;" ::: "memory");

        const u32 stb = sb + (u32)st * STAGEB;
        if (++st == STAGES) st = 0;
#pragma unroll
        for (int ks = 0; ks < 2; ks++) {
            u32 ah[4][4], al[4][4];
#pragma unroll
            for (int mt = 0; mt < 4; mt++) {
                const u32 arow = (u32)(wm * 64 + mt * 16 + ra);
                const u32 acb  = (u32)(((ks * 2 + ca) ^ swa) * 16);
                ldsm_x4(ah[mt][0], ah[mt][1], ah[mt][2], ah[mt][3], stb + arow * 64 + acb);
                ldsm_x4(al[mt][0], al[mt][1], al[mt][2], al[mt][3], stb + TILEB + arow * 64 + acb);
            }
#pragma unroll
            for (int p = 0; p < 2; p++) {
                u32 bh[4], bl[4];
                const u32 brow = (u32)(wn * 32 + p * 16 + rb);
                const u32 bcb  = (u32)(((ks * 2 + cbv) ^ swb) * 16);
                ldsm_x4(bh[0], bh[1], bh[2], bh[3], stb + 2 * TILEB + brow * 64 + bcb);
                ldsm_x4(bl[0], bl[1], bl[2], bl[3], stb + 3 * TILEB + brow * 64 + bcb);
#pragma unroll
                for (int mt = 0; mt < 4; mt++)
#pragma unroll
                    for (int h = 0; h < 2; h++) {
                        float* a4 = acc[mt][p * 2 + h];
                        mma_bf16(a4, ah[mt], bh[h * 2], bh[h * 2 + 1]);
                        mma_bf16(a4, ah[mt], bl[h * 2], bl[h * 2 + 1]);
                        mma_bf16(a4, al[mt], bh[h * 2], bh[h * 2 + 1]);
                    }
            }
        }
    }

    const int qrow = lane >> 2;
    const int qcol = (lane & 3) * 2;
#pragma unroll
    for (int mt = 0; mt < 4; mt++)
#pragma unroll
        for (int nt = 0; nt < 4; nt++) {
            const int r0 = bm + wm * 64 + mt * 16 + qrow;
            const int cc = bn + wn * 32 + nt * 8 + qcol;
            float2 lo0 = {acc[mt][nt][0], acc[mt][nt][1]};
            float2 lo1 = {acc[mt][nt][2], acc[mt][nt][3]};
            *(float2*)(C + (size_t)r0 * N + cc)       = lo0;
            *(float2*)(C + (size_t)(r0 + 8) * N + cc) = lo1;
        }
#undef LOAD_CHUNK
}

// ---------------------------------------------------------------------------
// Flash-style HMMA neighborhood attention.
// Block = one (b, head, 8x8 query tile): 128 threads, 4 warps.
// Warp w owns query rows 16w..16w+15 (m16). Key union window <= 196 keys,
// processed in 32-key tiles streamed via 3-stage cp.async pipeline.
// S = QhKh+QhKl+QlKh (bf16x3); P = masked exp(S*scale) packed in-register
// into A-fragments (FA2 trick); O += PhVh+PlVh+PhVl; final /rowsum.
// smem rows are 128B (64 bf16) with 16B-chunk swizzle: chunk ^= row&7.
// ---------------------------------------------------------------------------
#define NKPAD 224
#define AT_LUT_OFF   0
#define AT_QH_OFF    1024
#define AT_QL_OFF    (AT_QH_OFF + 8192)
#define AT_ST_OFF    (AT_QL_OFF + 8192)
#define AT_STAGEB    16384            // 4 arrays x 32 keys x 128B
#define AT_SMEM      (AT_ST_OFF + 3 * AT_STAGEB)   // 66560 B

__global__ __launch_bounds__(128, 3)
void nattn_mma(const __nv_bfloat16* __restrict__ Qh, const __nv_bfloat16* __restrict__ Ql,
               const __nv_bfloat16* __restrict__ Kh, const __nv_bfloat16* __restrict__ Kl,
               const __nv_bfloat16* __restrict__ Vh, const __nv_bfloat16* __restrict__ Vl,
               __nv_bfloat16* __restrict__ oh, __nv_bfloat16* __restrict__ ol)
{
    extern __shared__ char sma[];
    const u32 sb = smem_u32(sma);
    u32* lut = (u32*)sma;

    const int tid = threadIdx.x;
    const int wid = tid >> 5, lane = tid & 31;

    const int th = blockIdx.x >> 3;
    const int tw = blockIdx.x & 7;
    const int nh = blockIdx.y;
    const int b  = blockIdx.z;

    const int sh0 = max(th * 8 - 3, 0);
    const int KH  = min(th * 8 + 4, 57) + 7 - sh0;
    const int sw0 = max(tw * 8 - 3, 0);
    const int KW  = min(tw * 8 + 4, 57) + 7 - sw0;
    const int nk  = KH * KW;
    const int NKT = (nk + 31) >> 5;

    // ---- key LUT: key index -> (kh<<8)|kw ; pad = 0xFFFF ----
    for (int e = tid; e < NKPAD; e += 128) {
        u32 v = 0xFFFFu;
        if (e < nk) {
            const int kh = sh0 + e / KW;
            const int kw = sw0 + e - (e / KW) * KW;
            v = ((u32)kh << 8) | (u32)kw;
        }
        lut[e] = v;
    }
    __syncthreads();

    const size_t hoff = (size_t)(b * NHEADS + nh) * SEQ * DHEAD;
    const __nv_bfloat16* Qhp = Qh + hoff;
    const __nv_bfloat16* Qlp = Ql + hoff;
    const __nv_bfloat16* Khp = Kh + hoff;
    const __nv_bfloat16* Klp = Kl + hoff;
    const __nv_bfloat16* Vhp = Vh + hoff;
    const __nv_bfloat16* Vlp = Vl + hoff;

    // ---- stage Q (64 q-rows x 128B, hi+lo) ----
#pragma unroll
    for (int i = 0; i < 8; i++) {
        const int idx   = tid + i * 128;
        const int arr   = idx >> 9;                 // 0=Qh 1=Ql
        const int qrow  = (idx >> 3) & 63;
        const int chunk = idx & 7;
        const int qhh = th * 8 + (qrow >> 3);
        const int qww = tw * 8 + (qrow & 7);
        const int s = qhh * CAN + qww;
        const __nv_bfloat16* src = (arr ? Qlp : Qhp) + (size_t)s * 64 + chunk * 8;
        const u32 dst = sb + (arr ? AT_QL_OFF : AT_QH_OFF)
                        + (u32)qrow * 128 + (u32)((chunk ^ (qrow & 7)) << 4);
        cp16(dst, src);
    }
    asm volatile("cp.async.commit_group;" ::: "memory");

#define AT_STAGE(kt, stg)                                                          \
    {                                                                              \
        _Pragma("unroll")                                                          \
        for (int i = 0; i < 8; i++) {                                              \
            const int idx   = tid + i * 128;                                       \
            const int arr   = idx >> 8;            /* 0=Kh 1=Kl 2=Vh 3=Vl */       \
            const int key   = (idx >> 3) & 31;                                     \
            const int chunk = idx & 7;                                             \
            const u32 v = lut[(kt) * 32 + key];                                    \
            const __nv_bfloat16* base = (arr < 2) ? (arr ? Klp : Khp)              \
                                                  : (arr == 2 ? Vhp : Vlp);        \
            const void* src = (v == 0xFFFFu) ? (const void*)g_zero                 \
                : (const void*)(base + ((size_t)(v >> 8) * CAN + (v & 255u)) * 64  \
                                + chunk * 8);                                      \
            const u32 dst = sb + AT_ST_OFF + (u32)(stg) * AT_STAGEB                \
                            + (u32)arr * 4096u + (u32)key * 128u                   \
                            + (u32)((chunk ^ (key & 7)) << 4);                     \
            cp16(dst, src);                                                        \
        }                                                                          \
    }

    AT_STAGE(0, 0);
    asm volatile("cp.async.commit_group;" ::: "memory");
    if (NKT > 1) AT_STAGE(1, 1);
    asm volatile("cp.async.commit_group;" ::: "memory");

    // wait for Q; load Q a-fragments (held across mainloop)
    asm volatile("cp.async.wait_group %0;" :: "n"(2) : "memory");
    __syncthreads();

    u32 aqh[4][4], aql[4][4];
    {
        const int ra = lane & 15, ca = lane >> 4;
        const u32 qrow = (u32)(wid * 16 + ra);
#pragma unroll
        for (int ks = 0; ks < 4; ks++) {
            const u32 chunk = (u32)((ks * 2 + ca) ^ (qrow & 7));
            ldsm_x4(aqh[ks][0], aqh[ks][1], aqh[ks][2], aqh[ks][3],
                    sb + AT_QH_OFF + qrow * 128 + (chunk << 4));
            ldsm_x4(aql[ks][0], aql[ks][1], aql[ks][2], aql[ks][3],
                    sb + AT_QL_OFF + qrow * 128 + (chunk << 4));
        }
    }

    // per-thread query rows r0, r0+8 and their window starts
    const int r0 = wid * 16 + (lane >> 2);
    int sH0, sW0, sH1, sW1;
    {
        const int qh0 = th * 8 + (r0 >> 3),       qw0 = tw * 8 + (r0 & 7);
        const int r1 = r0 + 8;
        const int qh1 = th * 8 + (r1 >> 3),       qw1 = tw * 8 + (r1 & 7);
        sH0 = min(max(qh0 - 3, 0), 57); sW0 = min(max(qw0 - 3, 0), 57);
        sH1 = min(max(qh1 - 3, 0), 57); sW1 = min(max(qw1 - 3, 0), 57);
    }

    float oc[8][4];
#pragma unroll
    for (int i = 0; i < 8; i++)
#pragma unroll
        for (int j = 0; j < 4; j++) oc[i][j] = 0.f;
    float rs0 = 0.f, rs1 = 0.f;

    for (int kt = 0; kt < NKT; kt++) {
        asm volatile("cp.async.wait_group %0;" :: "n"(1) : "memory");
        __syncthreads();
        if (kt + 2 < NKT) AT_STAGE(kt + 2, (kt + 2) % 3);
        asm volatile("cp.async.commit_group;" ::: "memory");

        const u32 stb = sb + AT_ST_OFF + (u32)(kt % 3) * AT_STAGEB;

        // ---- S = Q K^T (m16 x n32 x k64, 3 terms) ----
        float sc[4][4];
#pragma unroll
        for (int i = 0; i < 4; i++)
#pragma unroll
            for (int j = 0; j < 4; j++) sc[i][j] = 0.f;

        const int rbk = (lane & 7) + ((lane >> 4) & 1) * 8;   // key row in n16 group
        const int cbk = (lane >> 3) & 1;
#pragma unroll
        for (int ks = 0; ks < 4; ks++) {
            u32 kbh[2][4], kbl[2][4];
#pragma unroll
            for (int g = 0; g < 2; g++) {                      // n16 groups
                const u32 krow = (u32)(g * 16 + rbk);
                const u32 chunk = (u32)((ks * 2 + cbk) ^ (krow & 7));
                ldsm_x4(kbh[g][0], kbh[g][1], kbh[g][2], kbh[g][3],
                        stb + 0 * 4096 + krow * 128 + (chunk << 4));
                ldsm_x4(kbl[g][0], kbl[g][1], kbl[g][2], kbl[g][3],
                        stb + 1 * 4096 + krow * 128 + (chunk << 4));
            }
#pragma unroll
            for (int nt = 0; nt < 4; nt++) {
                const int g = nt >> 1, h = (nt & 1) * 2;
                mma_bf16(sc[nt], aqh[ks], kbh[g][h], kbh[g][h + 1]);
                mma_bf16(sc[nt], aqh[ks], kbl[g][h], kbl[g][h + 1]);
                mma_bf16(sc[nt], aql[ks], kbh[g][h], kbh[g][h + 1]);
            }
        }

        // ---- mask + exp + pack P a-fragments ----
        u32 pah[2][4], pal[2][4];
#pragma unroll
        for (int nt = 0; nt < 4; nt++) {
            const int key0 = kt * 32 + nt * 8 + 2 * (lane & 3);
            const u32 v0 = lut[key0], v1 = lut[key0 + 1];
            const u32 kh0 = v0 >> 8, kw0 = v0 & 255u;
            const u32 kh1 = v1 >> 8, kw1 = v1 & 255u;
            const bool va0 = (kh0 - (u32)sH0 < 7u) && (kw0 - (u32)sW0 < 7u);
            const bool vb0 = (kh1 - (u32)sH0 < 7u) && (kw1 - (u32)sW0 < 7u);
            const bool va1 = (kh0 - (u32)sH1 < 7u) && (kw0 - (u32)sW1 < 7u);
            const bool vb1 = (kh1 - (u32)sH1 < 7u) && (kw1 - (u32)sW1 < 7u);
            const float p0 = va0 ? __expf(sc[nt][0] * 0.125f) : 0.f;
            const float p1 = vb0 ? __expf(sc[nt][1] * 0.125f) : 0.f;
            const float p2 = va1 ? __expf(sc[nt][2] * 0.125f) : 0.f;
            const float p3 = vb1 ? __expf(sc[nt][3] * 0.125f) : 0.f;
            rs0 += p0 + p1;
            rs1 += p2 + p3;
            const u32 ha = cvt_bf16x2(p1, p0);       // lo=p0 hi=p1
            const u32 hb = cvt_bf16x2(p3, p2);
            const u32 la = cvt_bf16x2(p1 - bf_hi(ha), p0 - bf_lo(ha));
            const u32 lb = cvt_bf16x2(p3 - bf_hi(hb), p2 - bf_lo(hb));
            const int t = nt >> 1, slot = (nt & 1) * 2;
            pah[t][slot] = ha; pah[t][slot + 1] = hb;
            pal[t][slot] = la; pal[t][slot + 1] = lb;
        }

        // ---- O += P V (m16 x n64 x k32, 3 terms), V via trans ldmatrix ----
#pragma unroll
        for (int ks2 = 0; ks2 < 2; ks2++) {
            u32 vbh[4][4], vbl[4][4];
            const u32 vrow = (u32)(ks2 * 16 + (lane & 15));
#pragma unroll
            for (int g = 0; g < 4; g++) {                      // n16 groups of d
                const u32 chunk = (u32)((g * 2 + (lane >> 4)) ^ (vrow & 7));
                ldsm_x4_t(vbh[g][0], vbh[g][1], vbh[g][2], vbh[g][3],
                          stb + 2 * 4096 + vrow * 128 + (chunk << 4));
                ldsm_x4_t(vbl[g][0], vbl[g][1], vbl[g][2], vbl[g][3],
                          stb + 3 * 4096 + vrow * 128 + (chunk << 4));
            }
#pragma unroll
            for (int nt = 0; nt < 8; nt++) {
                const int g = nt >> 1, h = (nt & 1) * 2;
                mma_bf16(oc[nt], pah[ks2], vbh[g][h], vbh[g][h + 1]);
                mma_bf16(oc[nt], pal[ks2], vbh[g][h], vbh[g][h + 1]);
                mma_bf16(oc[nt], pah[ks2], vbl[g][h], vbl[g][h + 1]);
            }
        }
    }

    // ---- rowsum reduce (quad) + normalized store as bf16 hi/lo ----
    rs0 += __shfl_xor_sync(0xffffffffu, rs0, 1);
    rs0 += __shfl_xor_sync(0xffffffffu, rs0, 2);
    rs1 += __shfl_xor_sync(0xffffffffu, rs1, 1);
    rs1 += __shfl_xor_sync(0xffffffffu, rs1, 2);
    const float inv0 = 1.0f / rs0;
    const float inv1 = 1.0f / rs1;

    const int qh0 = th * 8 + (r0 >> 3),  qw0 = tw * 8 + (r0 & 7);
    const int r1g = r0 + 8;
    const int qh1 = th * 8 + (r1g >> 3), qw1 = tw * 8 + (r1g & 7);
    const size_t ob0 = ((size_t)(b * SEQ + qh0 * CAN + qw0)) * DMODEL + nh * DHEAD;
    const size_t ob1 = ((size_t)(b * SEQ + qh1 * CAN + qw1)) * DMODEL + nh * DHEAD;

#pragma unroll
    for (int nt = 0; nt < 8; nt++) {
        const int d = nt * 8 + 2 * (lane & 3);
        const float a0 = oc[nt][0] * inv0, a1 = oc[nt][1] * inv0;
        const float a2 = oc[nt][2] * inv1, a3 = oc[nt][3] * inv1;
        const u32 h0 = cvt_bf16x2(a1, a0);
        const u32 l0 = cvt_bf16x2(a1 - bf_hi(h0), a0 - bf_lo(h0));
        const u32 h1 = cvt_bf16x2(a3, a2);
        const u32 l1 = cvt_bf16x2(a3 - bf_hi(h1), a2 - bf_lo(h1));
        *(u32*)(oh + ob0 + d) = h0;
        *(u32*)(ol + ob0 + d) = l0;
        *(u32*)(oh + ob1 + d) = h1;
        *(u32*)(ol + ob1 + d) = l1;
    }
#undef AT_STAGE
}

// ---------------------------------------------------------------------------
extern "C" void kernel_launch(void* const* d_in, const int* in_sizes, int n_in,
                              void* d_out, int out_size)
{
    const float* x     = (const float*)d_in[0];   // [8192,512]
    const float* w_qkv = (const float*)d_in[1];   // [1536,512]
    const float* w_out = (const float*)d_in[2];   // [512,512]
    float* out = (float*)d_out;                   // [8192,512]

    float* qkv;
    __nv_bfloat16 *xh, *xl, *wqh, *wql, *woh, *wol, *ath, *atl;
    __nv_bfloat16 *qh, *ql, *kh, *kl, *vh, *vl;
    cudaGetSymbolAddress((void**)&qkv, g_qkv);
    cudaGetSymbolAddress((void**)&xh,  g_xh);
    cudaGetSymbolAddress((void**)&xl,  g_xl);
    cudaGetSymbolAddress((void**)&wqh, g_wqh);
    cudaGetSymbolAddress((void**)&wql, g_wql);
    cudaGetSymbolAddress((void**)&woh, g_woh);
    cudaGetSymbolAddress((void**)&wol, g_wol);
    cudaGetSymbolAddress((void**)&ath, g_ath);
    cudaGetSymbolAddress((void**)&atl, g_atl);
    cudaGetSymbolAddress((void**)&qh,  g_Qh);
    cudaGetSymbolAddress((void**)&ql,  g_Ql);
    cudaGetSymbolAddress((void**)&kh,  g_Kh);
    cudaGetSymbolAddress((void**)&kl,  g_Kl);
    cudaGetSymbolAddress((void**)&vh,  g_Vh);
    cudaGetSymbolAddress((void**)&vl,  g_Vl);

    cudaFuncSetAttribute(gemm_mma, cudaFuncAttributeMaxDynamicSharedMemorySize, GEMM_SMEM);
    cudaFuncSetAttribute(nattn_mma, cudaFuncAttributeMaxDynamicSharedMemorySize, AT_SMEM);

    const int M = BATCH * SEQ;  // 8192

    // 0) split inputs to bf16 hi/lo
    split_kernel<<<(M * DMODEL / 4 + 255) / 256, 256>>>(x, xh, xl, M * DMODEL / 4);
    split_kernel<<<(3 * DMODEL * DMODEL / 4 + 255) / 256, 256>>>(w_qkv, wqh, wql,
                                                                 3 * DMODEL * DMODEL / 4);
    split_kernel<<<(DMODEL * DMODEL / 4 + 255) / 256, 256>>>(w_out, woh, wol,
                                                             DMODEL * DMODEL / 4);

    // 1) QKV projection: [8192,1536] fp32
    gemm_mma<<<dim3((3 * DMODEL) / 128, M / 128), 256, GEMM_SMEM>>>(
        xh, xl, wqh, wql, qkv, M, 3 * DMODEL, DMODEL);

    // 1b) split qkv into per-head bf16 hi/lo arrays
    qkv_split_kernel<<<(M * 384 + 255) / 256, 256>>>(qkv);

    // 2) flash-style neighborhood attention -> split bf16 [8192,512]
    nattn_mma<<<dim3(64, NHEADS, BATCH), 128, AT_SMEM>>>(qh, ql, kh, kl, vh, vl, ath, atl);

    // 3) output projection: [8192,512]
    gemm_mma<<<dim3(DMODEL / 128, M / 128), 256, GEMM_SMEM>>>(
        ath, atl, woh, wol, out, M, DMODEL, DMODEL);
}

// round 10
// speedup vs baseline: 1.3082x; 1.3082x over previous
#include <cuda_runtime.h>
#include <cuda_bf16.h>
#include <cstdint>

// Problem constants
#define SEQ    4096     // H*W
#define DMODEL 512
#define NHEADS 8
#define DHEAD  64
#define CAN    64       // canvas H = W
#define BATCH  2

typedef unsigned int u32;
typedef unsigned long long u64;
typedef unsigned short u16;

// Scratch (device globals: allocation-free rule)
__device__ float g_qkv[BATCH * SEQ * 3 * DMODEL];            // fp32 [b,s,1536]
__device__ __nv_bfloat16 g_xh[BATCH * SEQ * DMODEL];
__device__ __nv_bfloat16 g_xl[BATCH * SEQ * DMODEL];
__device__ __nv_bfloat16 g_wqh[3 * DMODEL * DMODEL];
__device__ __nv_bfloat16 g_wql[3 * DMODEL * DMODEL];
__device__ __nv_bfloat16 g_woh[DMODEL * DMODEL];
__device__ __nv_bfloat16 g_wol[DMODEL * DMODEL];
__device__ __nv_bfloat16 g_ath[BATCH * SEQ * DMODEL];
__device__ __nv_bfloat16 g_atl[BATCH * SEQ * DMODEL];

__device__ __forceinline__ u32 smem_u32(const void* p) {
    u32 a;
    asm("{ .reg .u64 t; cvta.to.shared.u64 t, %1; cvt.u32.u64 %0, t; }" : "=r"(a) : "l"(p));
    return a;
}
__device__ __forceinline__ u16 bfbits(__nv_bfloat16 h) { return *(u16*)&h; }

// ---------------------------------------------------------------------------
// fp32 -> bf16 hi/lo split (elementwise)
// ---------------------------------------------------------------------------
__global__ __launch_bounds__(256) void split_kernel(const float* __restrict__ in,
                                                    __nv_bfloat16* __restrict__ hi,
                                                    __nv_bfloat16* __restrict__ lo,
                                                    int n4)
{
    const int i = blockIdx.x * 256 + threadIdx.x;
    if (i >= n4) return;
    float4 f = ((const float4*)in)[i];
    float v[4] = {f.x, f.y, f.z, f.w};
    ushort4 hv, lv;
    u16* hp = &hv.x; u16* lp = &lv.x;
#pragma unroll
    for (int j = 0; j < 4; j++) {
        __nv_bfloat16 h = __float2bfloat16_rn(v[j]);
        __nv_bfloat16 l = __float2bfloat16_rn(v[j] - __bfloat162float(h));
        hp[j] = bfbits(h); lp[j] = bfbits(l);
    }
    ((ushort4*)hi)[i] = hv;
    ((ushort4*)lo)[i] = lv;
}

// ---------------------------------------------------------------------------
// bf16x3-split GEMM, cp.async 3-stage pipeline, 256 threads, 3 CTAs/SM.
// 64x128 CTA tile, K chunks of 32, warp tile 32x32 (2m x 4n).
// Per stage: Ah(4KB) | Al(4KB) | Bh(8KB) | Bl(8KB) = 24KB.
// ---------------------------------------------------------------------------
#define TILE_A  4096
#define TILE_B  8192
#define STAGEB  24576
#define STAGES  3
#define GEMM_SMEM (STAGES * STAGEB)   // 73728 B

__device__ __forceinline__ void ldsm_x4(u32& r0, u32& r1, u32& r2, u32& r3, u32 addr) {
    asm volatile("ldmatrix.sync.aligned.m8n8.x4.shared.b16 {%0,%1,%2,%3}, [%4];"
                 : "=r"(r0), "=r"(r1), "=r"(r2), "=r"(r3) : "r"(addr));
}
__device__ __forceinline__ void mma_bf16(float* c, const u32* a, u32 b0, u32 b1) {
    asm volatile("mma.sync.aligned.m16n8k16.row.col.f32.bf16.bf16.f32 "
                 "{%0,%1,%2,%3}, {%4,%5,%6,%7}, {%8,%9}, {%0,%1,%2,%3};"
                 : "+f"(c[0]), "+f"(c[1]), "+f"(c[2]), "+f"(c[3])
                 : "r"(a[0]), "r"(a[1]), "r"(a[2]), "r"(a[3]), "r"(b0), "r"(b1));
}
__device__ __forceinline__ void cp16(u32 daddr, const void* src) {
    asm volatile("cp.async.cg.shared.global [%0], [%1], 16;" :: "r"(daddr), "l"(src));
}

__global__ __launch_bounds__(256, 3)
void gemm_mma(const __nv_bfloat16* __restrict__ Ah, const __nv_bfloat16* __restrict__ Al,
              const __nv_bfloat16* __restrict__ Bh, const __nv_bfloat16* __restrict__ Bl,
              float* __restrict__ C, int M, int N, int K)
{
    extern __shared__ char smc[];
    const u32 sb = smem_u32(smc);

    const int tid  = threadIdx.x;
    const int wid  = tid >> 5, lane = tid & 31;
    const int wm   = wid & 1;          // 2 row halves of 32
    const int wn   = wid >> 1;         // 4 col groups of 32
    const int bm   = blockIdx.y * 64;
    const int bn   = blockIdx.x * 128;

    const int ra  = lane & 15;
    const int ca  = lane >> 4;
    const int swa = (ra >> 1) & 3;
    const int rb  = (lane & 7) + ((lane >> 4) & 1) * 8;
    const int cbv = (lane >> 3) & 1;
    const int swb = (rb >> 1) & 3;

    // loader per-thread constants
    const int lrow = tid >> 2;         // 0..63
    const int lc   = tid & 3;
    const u32 lsw  = (u32)((lc ^ ((lrow >> 1) & 3)) * 16);
    const u32 ldoff = (u32)lrow * 64u + lsw;

    float acc[2][4][4];
#pragma unroll
    for (int i = 0; i < 2; i++)
#pragma unroll
        for (int j = 0; j < 4; j++)
#pragma unroll
            for (int r = 0; r < 4; r++) acc[i][j][r] = 0.f;

    const int NC = K / 32;

#define LOAD_CHUNK(kc, stg)                                                        \
    {                                                                              \
        const u32 stbase = sb + (u32)(stg) * STAGEB;                               \
        const __nv_bfloat16* a_h = Ah + (size_t)(bm + lrow) * K + (kc) + lc * 8;   \
        const __nv_bfloat16* a_l = Al + (size_t)(bm + lrow) * K + (kc) + lc * 8;   \
        const __nv_bfloat16* b_h = Bh + (size_t)(bn + lrow) * K + (kc) + lc * 8;   \
        const __nv_bfloat16* b_l = Bl + (size_t)(bn + lrow) * K + (kc) + lc * 8;   \
        cp16(stbase + ldoff, a_h);                                                 \
        cp16(stbase + TILE_A + ldoff, a_l);                                        \
        cp16(stbase + 2 * TILE_A + ldoff, b_h);                                    \
        cp16(stbase + 2 * TILE_A + 4096u + ldoff, b_h + (size_t)64 * K);           \
        cp16(stbase + 2 * TILE_A + TILE_B + ldoff, b_l);                           \
        cp16(stbase + 2 * TILE_A + TILE_B + 4096u + ldoff, b_l + (size_t)64 * K);  \
    }

    LOAD_CHUNK(0, 0);
    asm volatile("cp.async.commit_group;" ::: "memory");
    LOAD_CHUNK(32, 1);
    asm volatile("cp.async.commit_group;" ::: "memory");

    int st = 0, ldst = 2;
    for (int ch = 0; ch < NC; ch++) {
        asm volatile("cp.async.wait_group %0;" :: "n"(1) : "memory");
        __syncthreads();

        if (ch + 2 < NC) {
            LOAD_CHUNK((ch + 2) * 32, ldst);
            if (++ldst == STAGES) ldst = 0;
        }
        asm volatile("cp.async.commit_group;" ::: "memory");

        const u32 stb = sb + (u32)st * STAGEB;
        if (++st == STAGES) st = 0;
#pragma unroll
        for (int ks = 0; ks < 2; ks++) {
            u32 ah[2][4], al[2][4];
#pragma unroll
            for (int mt = 0; mt < 2; mt++) {
                const u32 arow = (u32)(wm * 32 + mt * 16 + ra);
                const u32 acb  = (u32)(((ks * 2 + ca) ^ swa) * 16);
                ldsm_x4(ah[mt][0], ah[mt][1], ah[mt][2], ah[mt][3],
                        stb + arow * 64 + acb);
                ldsm_x4(al[mt][0], al[mt][1], al[mt][2], al[mt][3],
                        stb + TILE_A + arow * 64 + acb);
            }
#pragma unroll
            for (int p = 0; p < 2; p++) {
                u32 bh[4], bl[4];
                const u32 brow = (u32)(wn * 32 + p * 16 + rb);
                const u32 bcb  = (u32)(((ks * 2 + cbv) ^ swb) * 16);
                ldsm_x4(bh[0], bh[1], bh[2], bh[3],
                        stb + 2 * TILE_A + brow * 64 + bcb);
                ldsm_x4(bl[0], bl[1], bl[2], bl[3],
                        stb + 2 * TILE_A + TILE_B + brow * 64 + bcb);
#pragma unroll
                for (int mt = 0; mt < 2; mt++)
#pragma unroll
                    for (int h = 0; h < 2; h++) {
                        float* a4 = acc[mt][p * 2 + h];
                        mma_bf16(a4, ah[mt], bh[h * 2], bh[h * 2 + 1]);
                        mma_bf16(a4, ah[mt], bl[h * 2], bl[h * 2 + 1]);
                        mma_bf16(a4, al[mt], bh[h * 2], bh[h * 2 + 1]);
                    }
            }
        }
    }

    const int qrow = lane >> 2;
    const int qcol = (lane & 3) * 2;
#pragma unroll
    for (int mt = 0; mt < 2; mt++)
#pragma unroll
        for (int nt = 0; nt < 4; nt++) {
            const int r0 = bm + wm * 32 + mt * 16 + qrow;
            const int cc = bn + wn * 32 + nt * 8 + qcol;
            float2 lo0 = {acc[mt][nt][0], acc[mt][nt][1]};
            float2 lo1 = {acc[mt][nt][2], acc[mt][nt][3]};
            *(float2*)(C + (size_t)r0 * N + cc)       = lo0;
            *(float2*)(C + (size_t)(r0 + 8) * N + cc) = lo1;
        }
#undef LOAD_CHUNK
}

// ---------------------------------------------------------------------------
// packed fp32x2 helpers
// ---------------------------------------------------------------------------
__device__ __forceinline__ u64 pack2(float lo, float hi) {
    u64 r; asm("mov.b64 %0, {%1, %2};" : "=l"(r) : "f"(lo), "f"(hi)); return r;
}
__device__ __forceinline__ u64 dup2(float v) { return pack2(v, v); }
__device__ __forceinline__ void ffma2(u64& acc, u64 a, u64 b) {
    asm("fma.rn.f32x2 %0, %1, %2, %0;" : "+l"(acc) : "l"(a), "l"(b));
}
__device__ __forceinline__ float2 unpk2(u64 v) {
    float2 f; asm("mov.b64 {%0, %1}, %2;" : "=f"(f.x), "=f"(f.y) : "l"(v)); return f;
}

// ---------------------------------------------------------------------------
// Neighborhood attention (round-8 winner: XOR swizzle, 2 CTAs/SM).
// ---------------------------------------------------------------------------
#define KV_W(key, c4) (((key) << 6) + (((c4) ^ ((key) & 15)) << 2))
#define SS_STRIDE 51
#define SMEM_ATTN_BYTES ((196 * 64 * 2 + 64 * SS_STRIDE) * 4)

__global__ __launch_bounds__(256, 2) void nattn_kernel(const float* __restrict__ qkv,
                                                       __nv_bfloat16* __restrict__ oh,
                                                       __nv_bfloat16* __restrict__ ol)
{
    extern __shared__ float smf[];
    float* sk = smf;                       // [196*64] swizzled
    float* sv = smf + 196 * 64;            // [196*64] swizzled
    float* ss = sv + 196 * 64;             // [64][SS_STRIDE]

    const int th = blockIdx.x >> 3;
    const int tw = blockIdx.x & 7;
    const int nh = blockIdx.y;
    const int b  = blockIdx.z;

    const int sh0 = max(th * 8 - 3, 0);
    const int KH  = min(th * 8 + 4, 57) + 7 - sh0;
    const int sw0 = max(tw * 8 - 3, 0);
    const int KW  = min(tw * 8 + 4, 57) + 7 - sw0;

    const int tid = threadIdx.x;
    const int nk  = KH * KW;

    const float* kbase = qkv + (size_t)b * SEQ * (3 * DMODEL) + DMODEL + nh * DHEAD;
    const float* vbase = kbase + DMODEL;

    for (int idx = tid; idx < nk * 16; idx += 256) {
        const int key = idx >> 4;
        const int c4  = idx & 15;
        const int kh  = sh0 + key / KW;
        const int kw  = sw0 + key % KW;
        const size_t src = (size_t)(kh * CAN + kw) * (3 * DMODEL) + c4 * 4;
        float4 kd = *(const float4*)(kbase + src);
        float4 vd = *(const float4*)(vbase + src);
        *(float4*)(sk + KV_W(key, c4)) = kd;
        *(float4*)(sv + KV_W(key, c4)) = vd;
    }
    __syncthreads();

    const int q   = tid & 63;
    const int grp = tid >> 6;
    const int qy  = q >> 3, qx = q & 7;
    const int qh  = th * 8 + qy, qw = tw * 8 + qx;
    const int sH  = min(max(qh - 3, 0), 57);
    const int sW  = min(max(qw - 3, 0), 57);
    const int rH  = sH - sh0, rW = sW - sw0;
    const int s_q = qh * CAN + qw;

    // score phase: full 64-dim dots, keys j = grp, grp+4, ...
    {
        const float4* qp = (const float4*)(qkv + (size_t)(b * SEQ + s_q) * (3 * DMODEL)
                                           + nh * DHEAD);
        u64 qq[32];
#pragma unroll
        for (int t = 0; t < 16; t++) {
            float4 f = qp[t];
            qq[2 * t]     = pack2(f.x, f.y);
            qq[2 * t + 1] = pack2(f.z, f.w);
        }
        for (int j = grp; j < 49; j += 4) {
            const int a = j / 7, c = j - a * 7;
            const int key = (rH + a) * KW + rW + c;
            u64 d2 = 0ull;
#pragma unroll
            for (int t = 0; t < 16; t++) {
                float4 k = *(const float4*)(sk + KV_W(key, t));
                ffma2(d2, qq[2 * t],     pack2(k.x, k.y));
                ffma2(d2, qq[2 * t + 1], pack2(k.z, k.w));
            }
            float2 dp = unpk2(d2);
            ss[q * SS_STRIDE + j] = __expf((dp.x + dp.y) * 0.125f);
        }
    }
    __syncthreads();

    // softmax sum + AV (seg = grp owns 16 output dims)
    float wsum = 0.f;
#pragma unroll
    for (int j = 0; j < 49; j++) wsum += ss[q * SS_STRIDE + j];
    const float inv = 1.0f / wsum;

    u64 acc[8];
#pragma unroll
    for (int i = 0; i < 8; i++) acc[i] = 0ull;

    int jj = 0;
#pragma unroll
    for (int a = 0; a < 7; a++) {
#pragma unroll
        for (int c = 0; c < 7; c++) {
            const float w = ss[q * SS_STRIDE + jj];
            jj++;
            const u64 w2 = dup2(w);
            const int key = (rH + a) * KW + rW + c;
            float4 v0 = *(const float4*)(sv + KV_W(key, grp * 4 + 0));
            float4 v1 = *(const float4*)(sv + KV_W(key, grp * 4 + 1));
            float4 v2 = *(const float4*)(sv + KV_W(key, grp * 4 + 2));
            float4 v3 = *(const float4*)(sv + KV_W(key, grp * 4 + 3));
            ffma2(acc[0], w2, pack2(v0.x, v0.y));
            ffma2(acc[1], w2, pack2(v0.z, v0.w));
            ffma2(acc[2], w2, pack2(v1.x, v1.y));
            ffma2(acc[3], w2, pack2(v1.z, v1.w));
            ffma2(acc[4], w2, pack2(v2.x, v2.y));
            ffma2(acc[5], w2, pack2(v2.z, v2.w));
            ffma2(acc[6], w2, pack2(v3.x, v3.y));
            ffma2(acc[7], w2, pack2(v3.z, v3.w));
        }
    }

    float ov[16];
#pragma unroll
    for (int i = 0; i < 8; i++) {
        float2 p = unpk2(acc[i]);
        ov[i * 2]     = p.x * inv;
        ov[i * 2 + 1] = p.y * inv;
    }
    const size_t obase = (size_t)(b * SEQ + s_q) * DMODEL + nh * DHEAD + grp * 16;
#pragma unroll
    for (int g = 0; g < 4; g++) {
        ushort4 h4, l4;
        u16* hp = &h4.x; u16* lp = &l4.x;
#pragma unroll
        for (int j = 0; j < 4; j++) {
            const float v = ov[g * 4 + j];
            __nv_bfloat16 h = __float2bfloat16_rn(v);
            __nv_bfloat16 l = __float2bfloat16_rn(v - __bfloat162float(h));
            hp[j] = bfbits(h); lp[j] = bfbits(l);
        }
        *(ushort4*)(oh + obase + g * 4) = h4;
        *(ushort4*)(ol + obase + g * 4) = l4;
    }
}

// ---------------------------------------------------------------------------
extern "C" void kernel_launch(void* const* d_in, const int* in_sizes, int n_in,
                              void* d_out, int out_size)
{
    const float* x     = (const float*)d_in[0];   // [8192,512]
    const float* w_qkv = (const float*)d_in[1];   // [1536,512]
    const float* w_out = (const float*)d_in[2];   // [512,512]
    float* out = (float*)d_out;                   // [8192,512]

    float* qkv;
    __nv_bfloat16 *xh, *xl, *wqh, *wql, *woh, *wol, *ath, *atl;
    cudaGetSymbolAddress((void**)&qkv, g_qkv);
    cudaGetSymbolAddress((void**)&xh,  g_xh);
    cudaGetSymbolAddress((void**)&xl,  g_xl);
    cudaGetSymbolAddress((void**)&wqh, g_wqh);
    cudaGetSymbolAddress((void**)&wql, g_wql);
    cudaGetSymbolAddress((void**)&woh, g_woh);
    cudaGetSymbolAddress((void**)&wol, g_wol);
    cudaGetSymbolAddress((void**)&ath, g_ath);
    cudaGetSymbolAddress((void**)&atl, g_atl);

    cudaFuncSetAttribute(gemm_mma, cudaFuncAttributeMaxDynamicSharedMemorySize, GEMM_SMEM);
    cudaFuncSetAttribute(nattn_kernel, cudaFuncAttributeMaxDynamicSharedMemorySize,
                         SMEM_ATTN_BYTES);

    const int M = BATCH * SEQ;  // 8192

    // 0) split inputs to bf16 hi/lo
    split_kernel<<<(M * DMODEL / 4 + 255) / 256, 256>>>(x, xh, xl, M * DMODEL / 4);
    split_kernel<<<(3 * DMODEL * DMODEL / 4 + 255) / 256, 256>>>(w_qkv, wqh, wql,
                                                                 3 * DMODEL * DMODEL / 4);
    split_kernel<<<(DMODEL * DMODEL / 4 + 255) / 256, 256>>>(w_out, woh, wol,
                                                             DMODEL * DMODEL / 4);

    // 1) QKV projection: [8192,1536]
    gemm_mma<<<dim3((3 * DMODEL) / 128, M / 64), 256, GEMM_SMEM>>>(
        xh, xl, wqh, wql, qkv, M, 3 * DMODEL, DMODEL);

    // 2) neighborhood attention -> split bf16 [8192,512]
    nattn_kernel<<<dim3(64, NHEADS, BATCH), 256, SMEM_ATTN_BYTES>>>(qkv, ath, atl);

    // 3) output projection: [8192,512]
    gemm_mma<<<dim3(DMODEL / 128, M / 64), 256, GEMM_SMEM>>>(
        ath, atl, woh, wol, out, M, DMODEL, DMODEL);
}

// round 11
// speedup vs baseline: 1.4487x; 1.1074x over previous
#include <cuda_runtime.h>
#include <cuda_bf16.h>
#include <cstdint>

// Problem constants
#define SEQ    4096     // H*W
#define DMODEL 512
#define NHEADS 8
#define DHEAD  64
#define CAN    64       // canvas H = W
#define BATCH  2

typedef unsigned int u32;
typedef unsigned long long u64;
typedef unsigned short u16;

// Scratch (device globals: allocation-free rule)
__device__ float g_qkv[BATCH * SEQ * 3 * DMODEL];            // fp32 [b,s,1536]
__device__ __nv_bfloat16 g_xh[BATCH * SEQ * DMODEL];
__device__ __nv_bfloat16 g_xl[BATCH * SEQ * DMODEL];
__device__ __nv_bfloat16 g_wqh[3 * DMODEL * DMODEL];
__device__ __nv_bfloat16 g_wql[3 * DMODEL * DMODEL];
__device__ __nv_bfloat16 g_woh[DMODEL * DMODEL];
__device__ __nv_bfloat16 g_wol[DMODEL * DMODEL];
__device__ __nv_bfloat16 g_ath[BATCH * SEQ * DMODEL];
__device__ __nv_bfloat16 g_atl[BATCH * SEQ * DMODEL];

__device__ __forceinline__ u32 smem_u32(const void* p) {
    u32 a;
    asm("{ .reg .u64 t; cvta.to.shared.u64 t, %1; cvt.u32.u64 %0, t; }" : "=r"(a) : "l"(p));
    return a;
}
__device__ __forceinline__ u16 bfbits(__nv_bfloat16 h) { return *(u16*)&h; }

// ---------------------------------------------------------------------------
// fused fp32 -> bf16 hi/lo split for x, w_qkv, w_out (one launch)
// ---------------------------------------------------------------------------
#define N4_X  (BATCH * SEQ * DMODEL / 4)
#define N4_WQ (3 * DMODEL * DMODEL / 4)
#define N4_WO (DMODEL * DMODEL / 4)

__global__ __launch_bounds__(256) void split_all_kernel(const float* __restrict__ x,
                                                        const float* __restrict__ wq,
                                                        const float* __restrict__ wo)
{
    int i = blockIdx.x * 256 + threadIdx.x;
    const float* in;
    __nv_bfloat16 *hi, *lo;
    if (i < N4_X)                 { in = x;  hi = g_xh;  lo = g_xl; }
    else if ((i -= N4_X) < N4_WQ) { in = wq; hi = g_wqh; lo = g_wql; }
    else if ((i -= N4_WQ) < N4_WO){ in = wo; hi = g_woh; lo = g_wol; }
    else return;

    float4 f = ((const float4*)in)[i];
    float v[4] = {f.x, f.y, f.z, f.w};
    ushort4 hv, lv;
    u16* hp = &hv.x; u16* lp = &lv.x;
#pragma unroll
    for (int j = 0; j < 4; j++) {
        __nv_bfloat16 h = __float2bfloat16_rn(v[j]);
        __nv_bfloat16 l = __float2bfloat16_rn(v[j] - __bfloat162float(h));
        hp[j] = bfbits(h); lp[j] = bfbits(l);
    }
    ((ushort4*)hi)[i] = hv;
    ((ushort4*)lo)[i] = lv;
}

// ---------------------------------------------------------------------------
// bf16x3-split GEMM, cp.async 3-stage pipeline, 256 threads, 3 CTAs/SM.
// 64x128 CTA tile (round-10 winner, unchanged).
// ---------------------------------------------------------------------------
#define TILE_A  4096
#define TILE_B  8192
#define STAGEB  24576
#define STAGES  3
#define GEMM_SMEM (STAGES * STAGEB)   // 73728 B

__device__ __forceinline__ void ldsm_x4(u32& r0, u32& r1, u32& r2, u32& r3, u32 addr) {
    asm volatile("ldmatrix.sync.aligned.m8n8.x4.shared.b16 {%0,%1,%2,%3}, [%4];"
                 : "=r"(r0), "=r"(r1), "=r"(r2), "=r"(r3) : "r"(addr));
}
__device__ __forceinline__ void mma_bf16(float* c, const u32* a, u32 b0, u32 b1) {
    asm volatile("mma.sync.aligned.m16n8k16.row.col.f32.bf16.bf16.f32 "
                 "{%0,%1,%2,%3}, {%4,%5,%6,%7}, {%8,%9}, {%0,%1,%2,%3};"
                 : "+f"(c[0]), "+f"(c[1]), "+f"(c[2]), "+f"(c[3])
                 : "r"(a[0]), "r"(a[1]), "r"(a[2]), "r"(a[3]), "r"(b0), "r"(b1));
}
__device__ __forceinline__ void cp16(u32 daddr, const void* src) {
    asm volatile("cp.async.cg.shared.global [%0], [%1], 16;" :: "r"(daddr), "l"(src));
}

__global__ __launch_bounds__(256, 3)
void gemm_mma(const __nv_bfloat16* __restrict__ Ah, const __nv_bfloat16* __restrict__ Al,
              const __nv_bfloat16* __restrict__ Bh, const __nv_bfloat16* __restrict__ Bl,
              float* __restrict__ C, int M, int N, int K)
{
    extern __shared__ char smc[];
    const u32 sb = smem_u32(smc);

    const int tid  = threadIdx.x;
    const int wid  = tid >> 5, lane = tid & 31;
    const int wm   = wid & 1;
    const int wn   = wid >> 1;
    const int bm   = blockIdx.y * 64;
    const int bn   = blockIdx.x * 128;

    const int ra  = lane & 15;
    const int ca  = lane >> 4;
    const int swa = (ra >> 1) & 3;
    const int rb  = (lane & 7) + ((lane >> 4) & 1) * 8;
    const int cbv = (lane >> 3) & 1;
    const int swb = (rb >> 1) & 3;

    const int lrow = tid >> 2;
    const int lc   = tid & 3;
    const u32 lsw  = (u32)((lc ^ ((lrow >> 1) & 3)) * 16);
    const u32 ldoff = (u32)lrow * 64u + lsw;

    float acc[2][4][4];
#pragma unroll
    for (int i = 0; i < 2; i++)
#pragma unroll
        for (int j = 0; j < 4; j++)
#pragma unroll
            for (int r = 0; r < 4; r++) acc[i][j][r] = 0.f;

    const int NC = K / 32;

#define LOAD_CHUNK(kc, stg)                                                        \
    {                                                                              \
        const u32 stbase = sb + (u32)(stg) * STAGEB;                               \
        const __nv_bfloat16* a_h = Ah + (size_t)(bm + lrow) * K + (kc) + lc * 8;   \
        const __nv_bfloat16* a_l = Al + (size_t)(bm + lrow) * K + (kc) + lc * 8;   \
        const __nv_bfloat16* b_h = Bh + (size_t)(bn + lrow) * K + (kc) + lc * 8;   \
        const __nv_bfloat16* b_l = Bl + (size_t)(bn + lrow) * K + (kc) + lc * 8;   \
        cp16(stbase + ldoff, a_h);                                                 \
        cp16(stbase + TILE_A + ldoff, a_l);                                        \
        cp16(stbase + 2 * TILE_A + ldoff, b_h);                                    \
        cp16(stbase + 2 * TILE_A + 4096u + ldoff, b_h + (size_t)64 * K);           \
        cp16(stbase + 2 * TILE_A + TILE_B + ldoff, b_l);                           \
        cp16(stbase + 2 * TILE_A + TILE_B + 4096u + ldoff, b_l + (size_t)64 * K);  \
    }

    LOAD_CHUNK(0, 0);
    asm volatile("cp.async.commit_group;" ::: "memory");
    LOAD_CHUNK(32, 1);
    asm volatile("cp.async.commit_group;" ::: "memory");

    int st = 0, ldst = 2;
    for (int ch = 0; ch < NC; ch++) {
        asm volatile("cp.async.wait_group %0;" :: "n"(1) : "memory");
        __syncthreads();

        if (ch + 2 < NC) {
            LOAD_CHUNK((ch + 2) * 32, ldst);
            if (++ldst == STAGES) ldst = 0;
        }
        asm volatile("cp.async.commit_group;" ::: "memory");

        const u32 stb = sb + (u32)st * STAGEB;
        if (++st == STAGES) st = 0;
#pragma unroll
        for (int ks = 0; ks < 2; ks++) {
            u32 ah[2][4], al[2][4];
#pragma unroll
            for (int mt = 0; mt < 2; mt++) {
                const u32 arow = (u32)(wm * 32 + mt * 16 + ra);
                const u32 acb  = (u32)(((ks * 2 + ca) ^ swa) * 16);
                ldsm_x4(ah[mt][0], ah[mt][1], ah[mt][2], ah[mt][3],
                        stb + arow * 64 + acb);
                ldsm_x4(al[mt][0], al[mt][1], al[mt][2], al[mt][3],
                        stb + TILE_A + arow * 64 + acb);
            }
#pragma unroll
            for (int p = 0; p < 2; p++) {
                u32 bh[4], bl[4];
                const u32 brow = (u32)(wn * 32 + p * 16 + rb);
                const u32 bcb  = (u32)(((ks * 2 + cbv) ^ swb) * 16);
                ldsm_x4(bh[0], bh[1], bh[2], bh[3],
                        stb + 2 * TILE_A + brow * 64 + bcb);
                ldsm_x4(bl[0], bl[1], bl[2], bl[3],
                        stb + 2 * TILE_A + TILE_B + brow * 64 + bcb);
#pragma unroll
                for (int mt = 0; mt < 2; mt++)
#pragma unroll
                    for (int h = 0; h < 2; h++) {
                        float* a4 = acc[mt][p * 2 + h];
                        mma_bf16(a4, ah[mt], bh[h * 2], bh[h * 2 + 1]);
                        mma_bf16(a4, ah[mt], bl[h * 2], bl[h * 2 + 1]);
                        mma_bf16(a4, al[mt], bh[h * 2], bh[h * 2 + 1]);
                    }
            }
        }
    }

    const int qrow = lane >> 2;
    const int qcol = (lane & 3) * 2;
#pragma unroll
    for (int mt = 0; mt < 2; mt++)
#pragma unroll
        for (int nt = 0; nt < 4; nt++) {
            const int r0 = bm + wm * 32 + mt * 16 + qrow;
            const int cc = bn + wn * 32 + nt * 8 + qcol;
            float2 lo0 = {acc[mt][nt][0], acc[mt][nt][1]};
            float2 lo1 = {acc[mt][nt][2], acc[mt][nt][3]};
            *(float2*)(C + (size_t)r0 * N + cc)       = lo0;
            *(float2*)(C + (size_t)(r0 + 8) * N + cc) = lo1;
        }
#undef LOAD_CHUNK
}

// ---------------------------------------------------------------------------
// packed fp32x2 helpers
// ---------------------------------------------------------------------------
__device__ __forceinline__ u64 pack2(float lo, float hi) {
    u64 r; asm("mov.b64 %0, {%1, %2};" : "=l"(r) : "f"(lo), "f"(hi)); return r;
}
__device__ __forceinline__ u64 dup2(float v) { return pack2(v, v); }
__device__ __forceinline__ void ffma2(u64& acc, u64 a, u64 b) {
    asm("fma.rn.f32x2 %0, %1, %2, %0;" : "+l"(acc) : "l"(a), "l"(b));
}
__device__ __forceinline__ float2 unpk2(u64 v) {
    float2 f; asm("mov.b64 {%0, %1}, %2;" : "=f"(f.x), "=f"(f.y) : "l"(v)); return f;
}

// ---------------------------------------------------------------------------
// Neighborhood attention, XOR-swizzled K/V (stride 64), 2 CTAs/SM.
// Score phase: QUERY-PAIR sharing — thread = (pair p, union-column kg).
// Pair (qy,2qxp),(qy,2qxp+1) shares a 7 x UW (UW<=8) key-window union;
// each K row is read ONCE and dotted against both queries (score smem
// traffic 0.57x). Lanes 0..7 read 8 consecutive key rows -> conflict-free.
// AV phase unchanged (round-8 mapping).
// ---------------------------------------------------------------------------
#define KV_W(key, c4) (((key) << 6) + (((c4) ^ ((key) & 15)) << 2))
#define SS_STRIDE 51
#define SMEM_ATTN_BYTES ((196 * 64 * 2 + 64 * SS_STRIDE) * 4)

__global__ __launch_bounds__(256, 2) void nattn_kernel(const float* __restrict__ qkv,
                                                       __nv_bfloat16* __restrict__ oh,
                                                       __nv_bfloat16* __restrict__ ol)
{
    extern __shared__ float smf[];
    float* sk = smf;                       // [196*64] swizzled
    float* sv = smf + 196 * 64;            // [196*64] swizzled
    float* ss = sv + 196 * 64;             // [64][SS_STRIDE] (exp values)

    const int th = blockIdx.x >> 3;
    const int tw = blockIdx.x & 7;
    const int nh = blockIdx.y;
    const int b  = blockIdx.z;

    const int sh0 = max(th * 8 - 3, 0);
    const int KH  = min(th * 8 + 4, 57) + 7 - sh0;
    const int sw0 = max(tw * 8 - 3, 0);
    const int KW  = min(tw * 8 + 4, 57) + 7 - sw0;

    const int tid = threadIdx.x;
    const int nk  = KH * KW;

    const float* kbase = qkv + (size_t)b * SEQ * (3 * DMODEL) + DMODEL + nh * DHEAD;
    const float* vbase = kbase + DMODEL;

    // stage K/V union window (swizzled)
    for (int idx = tid; idx < nk * 16; idx += 256) {
        const int key = idx >> 4;
        const int c4  = idx & 15;
        const int kh  = sh0 + key / KW;
        const int kw  = sw0 + key % KW;
        const size_t src = (size_t)(kh * CAN + kw) * (3 * DMODEL) + c4 * 4;
        float4 kd = *(const float4*)(kbase + src);
        float4 vd = *(const float4*)(vbase + src);
        *(float4*)(sk + KV_W(key, c4)) = kd;
        *(float4*)(sv + KV_W(key, c4)) = vd;
    }
    __syncthreads();

    // ================= score phase: query pairs =================
    {
        const int kg  = tid & 7;            // union column
        const int p   = tid >> 3;           // pair 0..31
        const int qy  = p >> 2, qxp = p & 3;
        const int qw0 = tw * 8 + qxp * 2;
        const int qhh = th * 8 + qy;
        const int sH  = min(max(qhh - 3, 0), 57);
        const int sW0 = min(max(qw0 - 3, 0), 57);
        const int sW1 = min(max(qw0 - 2, 0), 57);
        const int dlt = sW1 - sW0;          // 0 or 1
        const int UW  = dlt + 7;
        const int rH  = sH - sh0;
        const int rWu = sW0 - sw0;
        const bool act = (kg < UW);
        const int q0t = qy * 8 + qxp * 2;   // tile-local query index
        const int s_q0 = qhh * CAN + qw0;

        u64 dot0[7], dot1[7];
#pragma unroll
        for (int a = 0; a < 7; a++) { dot0[a] = 0ull; dot1[a] = 0ull; }

        const float4* q0p = (const float4*)(qkv + (size_t)(b * SEQ + s_q0) * (3 * DMODEL)
                                            + nh * DHEAD);
        const float4* q1p = (const float4*)((const float*)q0p + 3 * DMODEL);

#pragma unroll
        for (int dc = 0; dc < 4; dc++) {
            u64 q0c[8], q1c[8];
#pragma unroll
            for (int j = 0; j < 4; j++) {
                float4 f0 = q0p[dc * 4 + j];
                q0c[2 * j]     = pack2(f0.x, f0.y);
                q0c[2 * j + 1] = pack2(f0.z, f0.w);
                float4 f1 = q1p[dc * 4 + j];
                q1c[2 * j]     = pack2(f1.x, f1.y);
                q1c[2 * j + 1] = pack2(f1.z, f1.w);
            }
#pragma unroll
            for (int a = 0; a < 7; a++) {
                if (act) {
                    const int key = (rH + a) * KW + rWu + kg;
#pragma unroll
                    for (int j = 0; j < 4; j++) {
                        float4 k = *(const float4*)(sk + KV_W(key, dc * 4 + j));
                        const u64 kp0 = pack2(k.x, k.y);
                        const u64 kp1 = pack2(k.z, k.w);
                        ffma2(dot0[a], q0c[2 * j],     kp0);
                        ffma2(dot0[a], q0c[2 * j + 1], kp1);
                        ffma2(dot1[a], q1c[2 * j],     kp0);
                        ffma2(dot1[a], q1c[2 * j + 1], kp1);
                    }
                }
            }
        }

        const bool v0 = (kg < 7);
        const bool v1 = (kg >= dlt) && ((kg - dlt) < 7);
#pragma unroll
        for (int a = 0; a < 7; a++) {
            float2 s0 = unpk2(dot0[a]);
            float2 s1 = unpk2(dot1[a]);
            if (v0) ss[q0t * SS_STRIDE + a * 7 + kg] =
                        __expf((s0.x + s0.y) * 0.125f);
            if (v1) ss[(q0t + 1) * SS_STRIDE + a * 7 + kg - dlt] =
                        __expf((s1.x + s1.y) * 0.125f);
        }
    }
    __syncthreads();

    // ================= softmax sum + AV (round-8 mapping) =================
    const int q   = tid & 63;
    const int grp = tid >> 6;
    const int qy  = q >> 3, qx = q & 7;
    const int qh  = th * 8 + qy, qw = tw * 8 + qx;
    const int sH  = min(max(qh - 3, 0), 57);
    const int sW  = min(max(qw - 3, 0), 57);
    const int rH  = sH - sh0, rW = sW - sw0;
    const int s_q = qh * CAN + qw;

    float wsum = 0.f;
#pragma unroll
    for (int j = 0; j < 49; j++) wsum += ss[q * SS_STRIDE + j];
    const float inv = 1.0f / wsum;

    u64 acc[8];
#pragma unroll
    for (int i = 0; i < 8; i++) acc[i] = 0ull;

    int jj = 0;
#pragma unroll
    for (int a = 0; a < 7; a++) {
#pragma unroll
        for (int c = 0; c < 7; c++) {
            const float w = ss[q * SS_STRIDE + jj];
            jj++;
            const u64 w2 = dup2(w);
            const int key = (rH + a) * KW + rW + c;
            float4 v0 = *(const float4*)(sv + KV_W(key, grp * 4 + 0));
            float4 v1 = *(const float4*)(sv + KV_W(key, grp * 4 + 1));
            float4 v2 = *(const float4*)(sv + KV_W(key, grp * 4 + 2));
            float4 v3 = *(const float4*)(sv + KV_W(key, grp * 4 + 3));
            ffma2(acc[0], w2, pack2(v0.x, v0.y));
            ffma2(acc[1], w2, pack2(v0.z, v0.w));
            ffma2(acc[2], w2, pack2(v1.x, v1.y));
            ffma2(acc[3], w2, pack2(v1.z, v1.w));
            ffma2(acc[4], w2, pack2(v2.x, v2.y));
            ffma2(acc[5], w2, pack2(v2.z, v2.w));
            ffma2(acc[6], w2, pack2(v3.x, v3.y));
            ffma2(acc[7], w2, pack2(v3.z, v3.w));
        }
    }

    float ov[16];
#pragma unroll
    for (int i = 0; i < 8; i++) {
        float2 p = unpk2(acc[i]);
        ov[i * 2]     = p.x * inv;
        ov[i * 2 + 1] = p.y * inv;
    }
    const size_t obase = (size_t)(b * SEQ + s_q) * DMODEL + nh * DHEAD + grp * 16;
#pragma unroll
    for (int g = 0; g < 4; g++) {
        ushort4 h4, l4;
        u16* hp = &h4.x; u16* lp = &l4.x;
#pragma unroll
        for (int j = 0; j < 4; j++) {
            const float v = ov[g * 4 + j];
            __nv_bfloat16 h = __float2bfloat16_rn(v);
            __nv_bfloat16 l = __float2bfloat16_rn(v - __bfloat162float(h));
            hp[j] = bfbits(h); lp[j] = bfbits(l);
        }
        *(ushort4*)(oh + obase + g * 4) = h4;
        *(ushort4*)(ol + obase + g * 4) = l4;
    }
}

// ---------------------------------------------------------------------------
extern "C" void kernel_launch(void* const* d_in, const int* in_sizes, int n_in,
                              void* d_out, int out_size)
{
    const float* x     = (const float*)d_in[0];   // [8192,512]
    const float* w_qkv = (const float*)d_in[1];   // [1536,512]
    const float* w_out = (const float*)d_in[2];   // [512,512]
    float* out = (float*)d_out;                   // [8192,512]

    float* qkv;
    __nv_bfloat16 *xh, *xl, *wqh, *wql, *woh, *wol, *ath, *atl;
    cudaGetSymbolAddress((void**)&qkv, g_qkv);
    cudaGetSymbolAddress((void**)&xh,  g_xh);
    cudaGetSymbolAddress((void**)&xl,  g_xl);
    cudaGetSymbolAddress((void**)&wqh, g_wqh);
    cudaGetSymbolAddress((void**)&wql, g_wql);
    cudaGetSymbolAddress((void**)&woh, g_woh);
    cudaGetSymbolAddress((void**)&wol, g_wol);
    cudaGetSymbolAddress((void**)&ath, g_ath);
    cudaGetSymbolAddress((void**)&atl, g_atl);

    cudaFuncSetAttribute(gemm_mma, cudaFuncAttributeMaxDynamicSharedMemorySize, GEMM_SMEM);
    cudaFuncSetAttribute(nattn_kernel, cudaFuncAttributeMaxDynamicSharedMemorySize,
                         SMEM_ATTN_BYTES);

    const int M = BATCH * SEQ;  // 8192

    // 0) fused split of x, w_qkv, w_out to bf16 hi/lo (single launch)
    {
        const int total = N4_X + N4_WQ + N4_WO;
        split_all_kernel<<<(total + 255) / 256, 256>>>(x, w_qkv, w_out);
    }

    // 1) QKV projection: [8192,1536]
    gemm_mma<<<dim3((3 * DMODEL) / 128, M / 64), 256, GEMM_SMEM>>>(
        xh, xl, wqh, wql, qkv, M, 3 * DMODEL, DMODEL);

    // 2) neighborhood attention -> split bf16 [8192,512]
    nattn_kernel<<<dim3(64, NHEADS, BATCH), 256, SMEM_ATTN_BYTES>>>(qkv, ath, atl);

    // 3) output projection: [8192,512]
    gemm_mma<<<dim3(DMODEL / 128, M / 64), 256, GEMM_SMEM>>>(
        ath, atl, woh, wol, out, M, DMODEL, DMODEL);
}

// round 12
// speedup vs baseline: 1.8413x; 1.2711x over previous
#include <cuda_runtime.h>
#include <cuda_bf16.h>
#include <cuda_fp16.h>
#include <cstdint>

// Problem constants
#define SEQ    4096     // H*W
#define DMODEL 512
#define NHEADS 8
#define DHEAD  64
#define CAN    64       // canvas H = W
#define BATCH  2

typedef unsigned int u32;
typedef unsigned long long u64;
typedef unsigned short u16;

// Scratch (device globals: allocation-free rule)
__device__ float g_qkv[BATCH * SEQ * 3 * DMODEL];            // fp32 [b,s,1536]
__device__ __half g_xh[BATCH * SEQ * DMODEL];                // x split hi/lo (fp16)
__device__ __half g_xl[BATCH * SEQ * DMODEL];
__device__ __half g_wqh[3 * DMODEL * DMODEL];                // w_qkv single fp16
__device__ __half g_woh[DMODEL * DMODEL];                    // w_out single fp16
__device__ __half g_ath[BATCH * SEQ * DMODEL];               // attn out hi/lo (fp16)
__device__ __half g_atl[BATCH * SEQ * DMODEL];

__device__ __forceinline__ u32 smem_u32(const void* p) {
    u32 a;
    asm("{ .reg .u64 t; cvta.to.shared.u64 t, %1; cvt.u32.u64 %0, t; }" : "=r"(a) : "l"(p));
    return a;
}
__device__ __forceinline__ u16 hfbits(__half h) { return *(u16*)&h; }

// ---------------------------------------------------------------------------
// fused split: x -> fp16 hi/lo ; w_qkv, w_out -> single fp16 (one launch)
// ---------------------------------------------------------------------------
#define N4_X  (BATCH * SEQ * DMODEL / 4)
#define N4_WQ (3 * DMODEL * DMODEL / 4)
#define N4_WO (DMODEL * DMODEL / 4)

__global__ __launch_bounds__(256) void split_all_kernel(const float* __restrict__ x,
                                                        const float* __restrict__ wq,
                                                        const float* __restrict__ wo)
{
    int i = blockIdx.x * 256 + threadIdx.x;
    if (i < N4_X) {
        float4 f = ((const float4*)x)[i];
        float v[4] = {f.x, f.y, f.z, f.w};
        ushort4 hv, lv;
        u16* hp = &hv.x; u16* lp = &lv.x;
#pragma unroll
        for (int j = 0; j < 4; j++) {
            __half h = __float2half_rn(v[j]);
            __half l = __float2half_rn(v[j] - __half2float(h));
            hp[j] = hfbits(h); lp[j] = hfbits(l);
        }
        ((ushort4*)g_xh)[i] = hv;
        ((ushort4*)g_xl)[i] = lv;
        return;
    }
    i -= N4_X;
    const float* in;
    __half* dst;
    if (i < N4_WQ)                  { in = wq; dst = g_wqh; }
    else if ((i -= N4_WQ) < N4_WO)  { in = wo; dst = g_woh; }
    else return;

    float4 f = ((const float4*)in)[i];
    float v[4] = {f.x, f.y, f.z, f.w};
    ushort4 hv;
    u16* hp = &hv.x;
#pragma unroll
    for (int j = 0; j < 4; j++) hp[j] = hfbits(__float2half_rn(v[j]));
    ((ushort4*)dst)[i] = hv;
}

// ---------------------------------------------------------------------------
// fp16 2-term GEMM:  C[M,N] = (Ah+Al)[M,K] @ Bh[N,K]^T
// cp.async 3-stage pipeline, 256 threads, 3 CTAs/SM, 64x128 CTA tile.
// Per stage: Ah(4KB) | Al(4KB) | Bh(8KB) = 16KB.
// ---------------------------------------------------------------------------
#define TILE_A  4096
#define TILE_B  8192
#define STAGEB  16384
#define STAGES  3
#define GEMM_SMEM (STAGES * STAGEB)   // 49152 B

__device__ __forceinline__ void ldsm_x4(u32& r0, u32& r1, u32& r2, u32& r3, u32 addr) {
    asm volatile("ldmatrix.sync.aligned.m8n8.x4.shared.b16 {%0,%1,%2,%3}, [%4];"
                 : "=r"(r0), "=r"(r1), "=r"(r2), "=r"(r3) : "r"(addr));
}
__device__ __forceinline__ void mma_fp16(float* c, const u32* a, u32 b0, u32 b1) {
    asm volatile("mma.sync.aligned.m16n8k16.row.col.f32.f16.f16.f32 "
                 "{%0,%1,%2,%3}, {%4,%5,%6,%7}, {%8,%9}, {%0,%1,%2,%3};"
                 : "+f"(c[0]), "+f"(c[1]), "+f"(c[2]), "+f"(c[3])
                 : "r"(a[0]), "r"(a[1]), "r"(a[2]), "r"(a[3]), "r"(b0), "r"(b1));
}
__device__ __forceinline__ void cp16(u32 daddr, const void* src) {
    asm volatile("cp.async.cg.shared.global [%0], [%1], 16;" :: "r"(daddr), "l"(src));
}

__global__ __launch_bounds__(256, 3)
void gemm_mma(const __half* __restrict__ Ah, const __half* __restrict__ Al,
              const __half* __restrict__ Bh,
              float* __restrict__ C, int M, int N, int K)
{
    extern __shared__ char smc[];
    const u32 sb = smem_u32(smc);

    const int tid  = threadIdx.x;
    const int wid  = tid >> 5, lane = tid & 31;
    const int wm   = wid & 1;          // 2 row halves of 32
    const int wn   = wid >> 1;         // 4 col groups of 32
    const int bm   = blockIdx.y * 64;
    const int bn   = blockIdx.x * 128;

    const int ra  = lane & 15;
    const int ca  = lane >> 4;
    const int swa = (ra >> 1) & 3;
    const int rb  = (lane & 7) + ((lane >> 4) & 1) * 8;
    const int cbv = (lane >> 3) & 1;
    const int swb = (rb >> 1) & 3;

    const int lrow = tid >> 2;
    const int lc   = tid & 3;
    const u32 lsw  = (u32)((lc ^ ((lrow >> 1) & 3)) * 16);
    const u32 ldoff = (u32)lrow * 64u + lsw;

    float acc[2][4][4];
#pragma unroll
    for (int i = 0; i < 2; i++)
#pragma unroll
        for (int j = 0; j < 4; j++)
#pragma unroll
            for (int r = 0; r < 4; r++) acc[i][j][r] = 0.f;

    const int NC = K / 32;

#define LOAD_CHUNK(kc, stg)                                                        \
    {                                                                              \
        const u32 stbase = sb + (u32)(stg) * STAGEB;                               \
        const __half* a_h = Ah + (size_t)(bm + lrow) * K + (kc) + lc * 8;          \
        const __half* a_l = Al + (size_t)(bm + lrow) * K + (kc) + lc * 8;          \
        const __half* b_h = Bh + (size_t)(bn + lrow) * K + (kc) + lc * 8;          \
        cp16(stbase + ldoff, a_h);                                                 \
        cp16(stbase + TILE_A + ldoff, a_l);                                        \
        cp16(stbase + 2 * TILE_A + ldoff, b_h);                                    \
        cp16(stbase + 2 * TILE_A + 4096u + ldoff, b_h + (size_t)64 * K);           \
    }

    LOAD_CHUNK(0, 0);
    asm volatile("cp.async.commit_group;" ::: "memory");
    LOAD_CHUNK(32, 1);
    asm volatile("cp.async.commit_group;" ::: "memory");

    int st = 0, ldst = 2;
    for (int ch = 0; ch < NC; ch++) {
        asm volatile("cp.async.wait_group %0;" :: "n"(1) : "memory");
        __syncthreads();

        if (ch + 2 < NC) {
            LOAD_CHUNK((ch + 2) * 32, ldst);
            if (++ldst == STAGES) ldst = 0;
        }
        asm volatile("cp.async.commit_group;" ::: "memory");

        const u32 stb = sb + (u32)st * STAGEB;
        if (++st == STAGES) st = 0;
#pragma unroll
        for (int ks = 0; ks < 2; ks++) {
            u32 ah[2][4], al[2][4];
#pragma unroll
            for (int mt = 0; mt < 2; mt++) {
                const u32 arow = (u32)(wm * 32 + mt * 16 + ra);
                const u32 acb  = (u32)(((ks * 2 + ca) ^ swa) * 16);
                ldsm_x4(ah[mt][0], ah[mt][1], ah[mt][2], ah[mt][3],
                        stb + arow * 64 + acb);
                ldsm_x4(al[mt][0], al[mt][1], al[mt][2], al[mt][3],
                        stb + TILE_A + arow * 64 + acb);
            }
#pragma unroll
            for (int p = 0; p < 2; p++) {
                u32 bh[4];
                const u32 brow = (u32)(wn * 32 + p * 16 + rb);
                const u32 bcb  = (u32)(((ks * 2 + cbv) ^ swb) * 16);
                ldsm_x4(bh[0], bh[1], bh[2], bh[3],
                        stb + 2 * TILE_A + brow * 64 + bcb);
#pragma unroll
                for (int mt = 0; mt < 2; mt++)
#pragma unroll
                    for (int h = 0; h < 2; h++) {
                        float* a4 = acc[mt][p * 2 + h];
                        mma_fp16(a4, ah[mt], bh[h * 2], bh[h * 2 + 1]);
                        mma_fp16(a4, al[mt], bh[h * 2], bh[h * 2 + 1]);
                    }
            }
        }
    }

    const int qrow = lane >> 2;
    const int qcol = (lane & 3) * 2;
#pragma unroll
    for (int mt = 0; mt < 2; mt++)
#pragma unroll
        for (int nt = 0; nt < 4; nt++) {
            const int r0 = bm + wm * 32 + mt * 16 + qrow;
            const int cc = bn + wn * 32 + nt * 8 + qcol;
            float2 lo0 = {acc[mt][nt][0], acc[mt][nt][1]};
            float2 lo1 = {acc[mt][nt][2], acc[mt][nt][3]};
            *(float2*)(C + (size_t)r0 * N + cc)       = lo0;
            *(float2*)(C + (size_t)(r0 + 8) * N + cc) = lo1;
        }
#undef LOAD_CHUNK
}

// ---------------------------------------------------------------------------
// packed fp32x2 helpers
// ---------------------------------------------------------------------------
__device__ __forceinline__ u64 pack2(float lo, float hi) {
    u64 r; asm("mov.b64 %0, {%1, %2};" : "=l"(r) : "f"(lo), "f"(hi)); return r;
}
__device__ __forceinline__ u64 dup2(float v) { return pack2(v, v); }
__device__ __forceinline__ void ffma2(u64& acc, u64 a, u64 b) {
    asm("fma.rn.f32x2 %0, %1, %2, %0;" : "+l"(acc) : "l"(a), "l"(b));
}
__device__ __forceinline__ float2 unpk2(u64 v) {
    float2 f; asm("mov.b64 {%0, %1}, %2;" : "=f"(f.x), "=f"(f.y) : "l"(v)); return f;
}

// ---------------------------------------------------------------------------
// Neighborhood attention (round-11 winner: XOR swizzle, query-pair scores,
// 2 CTAs/SM). Output written as fp16 hi/lo for GEMM2.
// ---------------------------------------------------------------------------
#define KV_W(key, c4) (((key) << 6) + (((c4) ^ ((key) & 15)) << 2))
#define SS_STRIDE 51
#define SMEM_ATTN_BYTES ((196 * 64 * 2 + 64 * SS_STRIDE) * 4)

__global__ __launch_bounds__(256, 2) void nattn_kernel(const float* __restrict__ qkv,
                                                       __half* __restrict__ oh,
                                                       __half* __restrict__ ol)
{
    extern __shared__ float smf[];
    float* sk = smf;                       // [196*64] swizzled
    float* sv = smf + 196 * 64;            // [196*64] swizzled
    float* ss = sv + 196 * 64;             // [64][SS_STRIDE] (exp values)

    const int th = blockIdx.x >> 3;
    const int tw = blockIdx.x & 7;
    const int nh = blockIdx.y;
    const int b  = blockIdx.z;

    const int sh0 = max(th * 8 - 3, 0);
    const int KH  = min(th * 8 + 4, 57) + 7 - sh0;
    const int sw0 = max(tw * 8 - 3, 0);
    const int KW  = min(tw * 8 + 4, 57) + 7 - sw0;

    const int tid = threadIdx.x;
    const int nk  = KH * KW;

    const float* kbase = qkv + (size_t)b * SEQ * (3 * DMODEL) + DMODEL + nh * DHEAD;
    const float* vbase = kbase + DMODEL;

    // stage K/V union window (swizzled)
    for (int idx = tid; idx < nk * 16; idx += 256) {
        const int key = idx >> 4;
        const int c4  = idx & 15;
        const int kh  = sh0 + key / KW;
        const int kw  = sw0 + key % KW;
        const size_t src = (size_t)(kh * CAN + kw) * (3 * DMODEL) + c4 * 4;
        float4 kd = *(const float4*)(kbase + src);
        float4 vd = *(const float4*)(vbase + src);
        *(float4*)(sk + KV_W(key, c4)) = kd;
        *(float4*)(sv + KV_W(key, c4)) = vd;
    }
    __syncthreads();

    // ================= score phase: query pairs =================
    {
        const int kg  = tid & 7;            // union column
        const int p   = tid >> 3;           // pair 0..31
        const int qy  = p >> 2, qxp = p & 3;
        const int qw0 = tw * 8 + qxp * 2;
        const int qhh = th * 8 + qy;
        const int sH  = min(max(qhh - 3, 0), 57);
        const int sW0 = min(max(qw0 - 3, 0), 57);
        const int sW1 = min(max(qw0 - 2, 0), 57);
        const int dlt = sW1 - sW0;          // 0 or 1
        const int UW  = dlt + 7;
        const int rH  = sH - sh0;
        const int rWu = sW0 - sw0;
        const bool act = (kg < UW);
        const int q0t = qy * 8 + qxp * 2;   // tile-local query index
        const int s_q0 = qhh * CAN + qw0;

        u64 dot0[7], dot1[7];
#pragma unroll
        for (int a = 0; a < 7; a++) { dot0[a] = 0ull; dot1[a] = 0ull; }

        const float4* q0p = (const float4*)(qkv + (size_t)(b * SEQ + s_q0) * (3 * DMODEL)
                                            + nh * DHEAD);
        const float4* q1p = (const float4*)((const float*)q0p + 3 * DMODEL);

#pragma unroll
        for (int dc = 0; dc < 4; dc++) {
            u64 q0c[8], q1c[8];
#pragma unroll
            for (int j = 0; j < 4; j++) {
                float4 f0 = q0p[dc * 4 + j];
                q0c[2 * j]     = pack2(f0.x, f0.y);
                q0c[2 * j + 1] = pack2(f0.z, f0.w);
                float4 f1 = q1p[dc * 4 + j];
                q1c[2 * j]     = pack2(f1.x, f1.y);
                q1c[2 * j + 1] = pack2(f1.z, f1.w);
            }
#pragma unroll
            for (int a = 0; a < 7; a++) {
                if (act) {
                    const int key = (rH + a) * KW + rWu + kg;
#pragma unroll
                    for (int j = 0; j < 4; j++) {
                        float4 k = *(const float4*)(sk + KV_W(key, dc * 4 + j));
                        const u64 kp0 = pack2(k.x, k.y);
                        const u64 kp1 = pack2(k.z, k.w);
                        ffma2(dot0[a], q0c[2 * j],     kp0);
                        ffma2(dot0[a], q0c[2 * j + 1], kp1);
                        ffma2(dot1[a], q1c[2 * j],     kp0);
                        ffma2(dot1[a], q1c[2 * j + 1], kp1);
                    }
                }
            }
        }

        const bool v0 = (kg < 7);
        const bool v1 = (kg >= dlt) && ((kg - dlt) < 7);
#pragma unroll
        for (int a = 0; a < 7; a++) {
            float2 s0 = unpk2(dot0[a]);
            float2 s1 = unpk2(dot1[a]);
            if (v0) ss[q0t * SS_STRIDE + a * 7 + kg] =
                        __expf((s0.x + s0.y) * 0.125f);
            if (v1) ss[(q0t + 1) * SS_STRIDE + a * 7 + kg - dlt] =
                        __expf((s1.x + s1.y) * 0.125f);
        }
    }
    __syncthreads();

    // ================= softmax sum + AV (round-8 mapping) =================
    const int q   = tid & 63;
    const int grp = tid >> 6;
    const int qy  = q >> 3, qx = q & 7;
    const int qh  = th * 8 + qy, qw = tw * 8 + qx;
    const int sH  = min(max(qh - 3, 0), 57);
    const int sW  = min(max(qw - 3, 0), 57);
    const int rH  = sH - sh0, rW = sW - sw0;
    const int s_q = qh * CAN + qw;

    float wsum = 0.f;
#pragma unroll
    for (int j = 0; j < 49; j++) wsum += ss[q * SS_STRIDE + j];
    const float inv = 1.0f / wsum;

    u64 acc[8];
#pragma unroll
    for (int i = 0; i < 8; i++) acc[i] = 0ull;

    int jj = 0;
#pragma unroll
    for (int a = 0; a < 7; a++) {
#pragma unroll
        for (int c = 0; c < 7; c++) {
            const float w = ss[q * SS_STRIDE + jj];
            jj++;
            const u64 w2 = dup2(w);
            const int key = (rH + a) * KW + rW + c;
            float4 v0 = *(const float4*)(sv + KV_W(key, grp * 4 + 0));
            float4 v1 = *(const float4*)(sv + KV_W(key, grp * 4 + 1));
            float4 v2 = *(const float4*)(sv + KV_W(key, grp * 4 + 2));
            float4 v3 = *(const float4*)(sv + KV_W(key, grp * 4 + 3));
            ffma2(acc[0], w2, pack2(v0.x, v0.y));
            ffma2(acc[1], w2, pack2(v0.z, v0.w));
            ffma2(acc[2], w2, pack2(v1.x, v1.y));
            ffma2(acc[3], w2, pack2(v1.z, v1.w));
            ffma2(acc[4], w2, pack2(v2.x, v2.y));
            ffma2(acc[5], w2, pack2(v2.z, v2.w));
            ffma2(acc[6], w2, pack2(v3.x, v3.y));
            ffma2(acc[7], w2, pack2(v3.z, v3.w));
        }
    }

    float ov[16];
#pragma unroll
    for (int i = 0; i < 8; i++) {
        float2 p = unpk2(acc[i]);
        ov[i * 2]     = p.x * inv;
        ov[i * 2 + 1] = p.y * inv;
    }
    const size_t obase = (size_t)(b * SEQ + s_q) * DMODEL + nh * DHEAD + grp * 16;
#pragma unroll
    for (int g = 0; g < 4; g++) {
        ushort4 h4, l4;
        u16* hp = &h4.x; u16* lp = &l4.x;
#pragma unroll
        for (int j = 0; j < 4; j++) {
            const float v = ov[g * 4 + j];
            __half h = __float2half_rn(v);
            __half l = __float2half_rn(v - __half2float(h));
            hp[j] = hfbits(h); lp[j] = hfbits(l);
        }
        *(ushort4*)(oh + obase + g * 4) = h4;
        *(ushort4*)(ol + obase + g * 4) = l4;
    }
}

// ---------------------------------------------------------------------------
extern "C" void kernel_launch(void* const* d_in, const int* in_sizes, int n_in,
                              void* d_out, int out_size)
{
    const float* x     = (const float*)d_in[0];   // [8192,512]
    const float* w_qkv = (const float*)d_in[1];   // [1536,512]
    const float* w_out = (const float*)d_in[2];   // [512,512]
    float* out = (float*)d_out;                   // [8192,512]

    float* qkv;
    __half *xh, *xl, *wqh, *woh, *ath, *atl;
    cudaGetSymbolAddress((void**)&qkv, g_qkv);
    cudaGetSymbolAddress((void**)&xh,  g_xh);
    cudaGetSymbolAddress((void**)&xl,  g_xl);
    cudaGetSymbolAddress((void**)&wqh, g_wqh);
    cudaGetSymbolAddress((void**)&woh, g_woh);
    cudaGetSymbolAddress((void**)&ath, g_ath);
    cudaGetSymbolAddress((void**)&atl, g_atl);

    cudaFuncSetAttribute(gemm_mma, cudaFuncAttributeMaxDynamicSharedMemorySize, GEMM_SMEM);
    cudaFuncSetAttribute(nattn_kernel, cudaFuncAttributeMaxDynamicSharedMemorySize,
                         SMEM_ATTN_BYTES);

    const int M = BATCH * SEQ;  // 8192

    // 0) fused split (x -> fp16 hi/lo; weights -> single fp16), one launch
    {
        const int total = N4_X + N4_WQ + N4_WO;
        split_all_kernel<<<(total + 255) / 256, 256>>>(x, w_qkv, w_out);
    }

    // 1) QKV projection: [8192,1536]
    gemm_mma<<<dim3((3 * DMODEL) / 128, M / 64), 256, GEMM_SMEM>>>(
        xh, xl, wqh, qkv, M, 3 * DMODEL, DMODEL);

    // 2) neighborhood attention -> fp16 hi/lo [8192,512]
    nattn_kernel<<<dim3(64, NHEADS, BATCH), 256, SMEM_ATTN_BYTES>>>(qkv, ath, atl);

    // 3) output projection: [8192,512]
    gemm_mma<<<dim3(DMODEL / 128, M / 64), 256, GEMM_SMEM>>>(
        ath, atl, woh, out, M, DMODEL, DMODEL);
}